// round 5
// baseline (speedup 1.0000x reference)
#include <cuda_runtime.h>
#include <cstdint>

#define BB 8
#define TT 128
#define DD 512
#define OO 512
#define CPG 8              // CTAs per cluster (one cluster per batch)
#define OSL (OO/CPG)       // 64  output-col slice per CTA
#define NTH 512
#define FULLMASK 0xffffffffu

// ---------------- device scratch (no allocations allowed) ----------------
__device__ float g_UaH[BB*TT*OO];   // inputs@Ua + Ba
__device__ float g_IC [BB*TT*OO];   // inputs@Co
__device__ float g_XUo[BB*TT*OO];   // inputs@Uo
__device__ float g_embWo[OO];       // emb@Wo

// ---------------- helpers ----------------
__device__ __forceinline__ float wredsum(float v) {
    #pragma unroll
    for (int s = 16; s; s >>= 1) v += __shfl_xor_sync(FULLMASK, v, s);
    return v;
}
__device__ __forceinline__ float tanhapx(float x) {
    float y;
    asm("tanh.approx.f32 %0, %1;" : "=f"(y) : "f"(x));
    return y;
}
__device__ __forceinline__ uint32_t smem_u32(const void* p) {
    uint32_t a;
    asm("{ .reg .u64 t; cvta.to.shared.u64 t, %1; cvt.u32.u64 %0, t; }"
        : "=r"(a) : "l"(p));
    return a;
}
__device__ __forceinline__ uint32_t dsm_map(uint32_t laddr, uint32_t rank) {
    uint32_t r;
    asm("mapa.shared::cluster.u32 %0, %1, %2;" : "=r"(r) : "r"(laddr), "r"(rank));
    return r;
}
__device__ __forceinline__ void dsm_st(uint32_t raddr, float v) {
    asm volatile("st.shared::cluster.f32 [%0], %1;" :: "r"(raddr), "f"(v) : "memory");
}
__device__ __forceinline__ void mbar_init(uint32_t a, uint32_t cnt) {
    asm volatile("mbarrier.init.shared.b64 [%0], %1;" :: "r"(a), "r"(cnt) : "memory");
}
__device__ __forceinline__ void mbar_arrive_remote(uint32_t raddr) {
    asm volatile("mbarrier.arrive.release.cluster.shared::cluster.b64 _, [%0];"
                 :: "r"(raddr) : "memory");
}
__device__ __forceinline__ void mbar_wait(uint32_t a, uint32_t parity) {
    asm volatile(
        "{\n\t.reg .pred P;\n\t"
        "W_%=:\n\t"
        "mbarrier.try_wait.parity.acquire.cluster.shared::cta.b64 P, [%0], %1, 0x989680;\n\t"
        "@!P bra W_%=;\n\t}"
        :: "r"(a), "r"(parity) : "memory");
}
#define CLUSTER_SYNC() do { \
    asm volatile("barrier.cluster.arrive.aligned;" ::: "memory"); \
    asm volatile("barrier.cluster.wait.aligned;"   ::: "memory"); \
} while (0)

// packed fp32x2 fma: d = a*b + d  (two lanes per instruction)
__device__ __forceinline__ void fma2(unsigned long long& d,
                                     unsigned long long a, unsigned long long b) {
    asm("fma.rn.f32x2 %0, %1, %2, %0;" : "+l"(d) : "l"(a), "l"(b));
}
__device__ __forceinline__ unsigned long long pack2(float x, float y) {
    unsigned long long r;
    asm("mov.b64 %0, {%1, %2};" : "=l"(r) : "f"(x), "f"(y));
    return r;
}
__device__ __forceinline__ float2 unpack2(unsigned long long v) {
    float2 r;
    asm("mov.b64 {%0, %1}, %2;" : "=f"(r.x), "=f"(r.y) : "l"(v));
    return r;
}

// =======================================================================
// GEMM (fp32x2): C_z = A[1024x512] @ B_z[512x512], z=0:Ua(+Ba),1:Co,2:Uo
// 64x64 tile, BK=16, 256 threads, 4x4 per thread via 8 packed accumulators.
// B tile stored pre-duplicated (b,b) so the inner loop has no packing ALU.
// =======================================================================
__global__ __launch_bounds__(256) void gemm3_kernel(
    const float* __restrict__ A,
    const float* __restrict__ Ua,
    const float* __restrict__ Co,
    const float* __restrict__ Uo,
    const float* __restrict__ Ba)
{
    __shared__ float As[16][64];                 // k-major, m contiguous
    __shared__ unsigned long long Bs2[16][64];   // (b,b) duplicated pairs

    const int m0 = blockIdx.x * 64;
    const int n0 = blockIdx.y * 64;
    const int z  = blockIdx.z;
    const float* __restrict__ Bm = (z == 0) ? Ua : ((z == 1) ? Co : Uo);
    float* Cout = (z == 0) ? g_UaH : ((z == 1) ? g_IC : g_XUo);

    const int tid  = threadIdx.x;
    const int tx   = tid & 15;
    const int ty   = tid >> 4;
    const int la_m = tid >> 2;
    const int la_k = (tid & 3) << 2;
    const int lb_k = tid >> 4;
    const int lb_n = (tid & 15) << 2;

    unsigned long long acc[2][4];   // [m-pair][n] ; pair = (m, m+1)
    #pragma unroll
    for (int i = 0; i < 2; i++)
        #pragma unroll
        for (int j = 0; j < 4; j++) acc[i][j] = 0ull;

    for (int k0 = 0; k0 < DD; k0 += 16) {
        float4 av = *(const float4*)&A [(m0 + la_m) * DD + k0 + la_k];
        float4 bv = *(const float4*)&Bm[(k0 + lb_k) * OO + n0 + lb_n];
        __syncthreads();
        As[la_k + 0][la_m] = av.x;
        As[la_k + 1][la_m] = av.y;
        As[la_k + 2][la_m] = av.z;
        As[la_k + 3][la_m] = av.w;
        Bs2[lb_k][lb_n + 0] = pack2(bv.x, bv.x);
        Bs2[lb_k][lb_n + 1] = pack2(bv.y, bv.y);
        Bs2[lb_k][lb_n + 2] = pack2(bv.z, bv.z);
        Bs2[lb_k][lb_n + 3] = pack2(bv.w, bv.w);
        __syncthreads();
        #pragma unroll
        for (int kk = 0; kk < 16; kk++) {
            double2 ad = *(const double2*)&As[kk][ty << 2];
            unsigned long long a01 = __double_as_longlong(ad.x);
            unsigned long long a23 = __double_as_longlong(ad.y);
            ulonglong2 bb0 = *(const ulonglong2*)&Bs2[kk][tx << 2];
            ulonglong2 bb1 = *(const ulonglong2*)&Bs2[kk][(tx << 2) + 2];
            fma2(acc[0][0], a01, bb0.x); fma2(acc[1][0], a23, bb0.x);
            fma2(acc[0][1], a01, bb0.y); fma2(acc[1][1], a23, bb0.y);
            fma2(acc[0][2], a01, bb1.x); fma2(acc[1][2], a23, bb1.x);
            fma2(acc[0][3], a01, bb1.y); fma2(acc[1][3], a23, bb1.y);
        }
    }
    #pragma unroll
    for (int mp = 0; mp < 2; mp++) {
        #pragma unroll
        for (int j = 0; j < 4; j++) {
            float2 v = unpack2(acc[mp][j]);
            int r = m0 + (ty << 2) + (mp << 1);
            int c = n0 + (tx << 2) + j;
            float add = (z == 0) ? Ba[c] : 0.f;
            Cout[(size_t)r       * OO + c] = v.x + add;
            Cout[(size_t)(r + 1) * OO + c] = v.y + add;
        }
    }
}

// =======================================================================
// embWo[i] = sum_j emb[i][j] * Wo[j]   (one warp per row)
// =======================================================================
__global__ __launch_bounds__(256) void embwo_kernel(
    const float* __restrict__ emb, const float* __restrict__ Wo)
{
    const int row  = (blockIdx.x << 3) + (threadIdx.x >> 5);
    const int lane = threadIdx.x & 31;
    const float* rp = emb + row * OO;
    float acc = 0.f;
    #pragma unroll 4
    for (int j = lane; j < OO; j += 32) acc += rp[j] * Wo[j];
    acc = wredsum(acc);
    if (lane == 0) g_embWo[row] = acc;
}

// =======================================================================
// Persistent clustered scan, 512 threads, mbarrier cluster sync.
// =======================================================================
#define UAH_PITCH 65
// shared memory layout (float offsets)
#define UAH_OFF   0                            // [128][65] = 8320
#define IC_OFF    (UAH_OFF + TT*UAH_PITCH)     // [128][64] = 8192
#define PRED_OFF  (IC_OFF + TT*OSL)            // [512]  broadcast target
#define SIG_OFF   (PRED_OFF + OO)              // [512]
#define SPART_OFF (SIG_OFF + OO)               // [8][128] broadcast target
#define WBUF_OFF  (SPART_OFF + CPG*TT)         // [128]
#define WAS_OFF   (WBUF_OFF + TT)              // [64]
#define VA_OFF    (WAS_OFF + OSL)              // [64]
#define RED_OFF   (VA_OFF + OSL)               // [48]
#define PART_OFF  (RED_OFF + 48)               // [512]
#define BAR_OFF   (PART_OFF + 512)             // 2 x u64 mbarrier (8B aligned)
#define SMEM_FLOATS (BAR_OFF + 4)
#define SMEM_BYTES  (SMEM_FLOATS * 4)

__global__ __launch_bounds__(NTH, 1) __cluster_dims__(CPG, 1, 1)
void scan_kernel(const float* __restrict__ Wa,
                 const float* __restrict__ Va,
                 const float* __restrict__ Bo,
                 float* __restrict__ out)
{
    extern __shared__ float sm[];
    float* UaH_s  = sm + UAH_OFF;
    float* IC_s   = sm + IC_OFF;
    float* pred_s = sm + PRED_OFF;
    float* sig_s  = sm + SIG_OFF;
    float* spart  = sm + SPART_OFF;
    float* wbuf   = sm + WBUF_OFF;
    float* WaS_s  = sm + WAS_OFF;
    float* va_s   = sm + VA_OFF;
    float* red    = sm + RED_OFF;
    float* part   = sm + PART_OFF;

    const uint32_t sbase    = smem_u32(sm);
    const uint32_t barA_l   = sbase + BAR_OFF * 4;
    const uint32_t barB_l   = barA_l + 8;

    const int tid  = threadIdx.x;
    const int lane = tid & 31;
    const int wid  = tid >> 5;
    const int b    = blockIdx.x >> 3;     // batch
    const int crk  = blockIdx.x & 7;      // cluster rank
    const int o_base = crk * OSL;
    const int oc  = tid & 63;             // o within slice   (P1 WaS / P3 ctx)
    const int kc8 = tid >> 6;             // 1/8 split        (P1 WaS / P3 ctx)
    const int ts  = tid & 127;            // timestep         (P2)
    const int q   = tid >> 7;             // o quarter        (P2)

    // ---------------- prologue ----------------
    for (int i = tid; i < TT * OSL; i += NTH) {
        int tt = i >> 6, o = i & 63;
        UaH_s[tt * UAH_PITCH + o] = g_UaH[(size_t)(b * TT + tt) * OO + o_base + o];
        IC_s[(tt << 6) + o]       = g_IC [(size_t)(b * TT + tt) * OO + o_base + o];
    }
    for (int i = tid; i < OO; i += NTH) pred_s[i] = 0.f;
    if (tid < OSL) va_s[tid] = Va[o_base + tid];

    // Wa slice in registers: thread (oc, kc8) holds Wa[kc8*64+i][o_base+oc]
    float wreg[64];
    #pragma unroll
    for (int i = 0; i < 64; i++)
        wreg[i] = Wa[(size_t)(kc8 * 64 + i) * OO + o_base + oc];

    const float ew   = g_embWo[tid];
    const float bo_r = (tid < OSL) ? Bo[o_base + tid] : 0.f;

    // loop-invariant remote addresses
    uint32_t sc_raddr[CPG];    // spart[crk][ts]        (used by tid<128)
    uint32_t pr_raddr[CPG];    // pred_s[o_base+oc]     (used by tid<64)
    {
        uint32_t a1 = sbase + (uint32_t)(SPART_OFF + crk * TT + ts) * 4u;
        uint32_t a2 = sbase + (uint32_t)(PRED_OFF + o_base + oc) * 4u;
        #pragma unroll
        for (int r = 0; r < CPG; r++) {
            sc_raddr[r] = dsm_map(a1, r);
            pr_raddr[r] = dsm_map(a2, r);
        }
    }
    const uint32_t barA_r = dsm_map(barA_l, tid & 7);   // rank = tid (tid<8)
    const uint32_t barB_r = dsm_map(barB_l, tid & 7);

    if (tid == 0) { mbar_init(barA_l, CPG); mbar_init(barB_l, CPG); }
    __syncthreads();
    CLUSTER_SYNC();   // barriers initialized everywhere before any remote op

    // ---------------- scan over T steps ----------------
    for (int t = 0; t < TT; t++) {
        const uint32_t par = t & 1;

        // prefetch XUo[b, (t-1) mod T, own o-slice]
        float xo = 0.f;
        if (tid < OSL)
            xo = __ldg(&g_XUo[(size_t)(b * TT + ((t + TT - 1) & (TT - 1))) * OO + o_base + tid]);

        // ============ P1: exp/sigmoid + partial reductions + WaS ============
        float pv = pred_s[tid];
        float e  = __expf(pv);                    // |pred| < ~4: no max-sub
        sig_s[tid] = __fdividef(1.f, 1.f + __expf(-pv));
        float ps = wredsum(e);
        float pd = wredsum(e * ew);
        if (lane == 0) { red[wid] = ps; red[16 + wid] = pd; }
        __syncthreads();                           // (1) red[0..31] + sig_s

        // WaS partial: thread (oc,kc8) covers k in [kc8*64, kc8*64+64)
        {
            const float4* sp4 = (const float4*)(sig_s + (kc8 << 6));
            float acc = 0.f;
            #pragma unroll
            for (int i = 0; i < 16; i++) {
                float4 s4 = sp4[i];
                acc += s4.x * wreg[4*i]   + s4.y * wreg[4*i+1]
                     + s4.z * wreg[4*i+2] + s4.w * wreg[4*i+3];
            }
            part[tid] = acc;
        }
        __syncthreads();                           // (2)
        if (tid < OSL) {
            float w = 0.f;
            #pragma unroll
            for (int j = 0; j < 8; j++) w += part[(j << 6) + tid];
            WaS_s[tid] = w;
        }
        __syncthreads();                           // (3) WaS_s ready

        // ============ P2: partial scores, all t, own o-quarter ============
        {
            const float* urow = UaH_s + ts * UAH_PITCH + (q << 4);
            const float* wp   = WaS_s + (q << 4);
            const float* vp   = va_s  + (q << 4);
            float acc = 0.f;
            #pragma unroll
            for (int i = 0; i < 16; i++)
                acc += tanhapx(urow[i] + wp[i]) * vp[i];
            part[(q << 7) + ts] = acc;
        }
        __syncthreads();                           // (4)
        if (tid < TT) {
            float s = part[tid] + part[128 + tid] + part[256 + tid] + part[384 + tid];
            #pragma unroll
            for (int r = 0; r < CPG; r++) dsm_st(sc_raddr[r], s);
            asm volatile("bar.sync 1, 128;" ::: "memory");
            if (tid < CPG) mbar_arrive_remote(barA_r);
        }
        mbar_wait(barA_l, par);                    // spart complete

        // ============ P3: softmax over T + ctx + pred ============
        if (tid < TT) {
            float sc = 0.f;
            #pragma unroll
            for (int r = 0; r < CPG; r++) sc += spart[(r << 7) + tid];
            float esv = __expf(sc);                // |score| small: no max-sub
            wbuf[tid] = esv;
            float spp = wredsum(esv);
            if (lane == 0) red[32 + wid] = spp;
        }
        __syncthreads();                           // (5) wbuf + red[32..35]
        const float esum = (red[32] + red[33]) + (red[34] + red[35]);

        // ctx partial: thread (oc,kc8) covers t' in [kc8*16, kc8*16+16)
        {
            float acc = 0.f;
            const int base = kc8 << 4;
            #pragma unroll
            for (int i = 0; i < 16; i++)
                acc += wbuf[base + i] * IC_s[((base + i) << 6) + oc];
            part[tid] = acc;
        }
        __syncthreads();                           // (6)
        if (tid < OSL) {
            float S = 0.f, P = 0.f;
            #pragma unroll
            for (int j = 0; j < 16; j++) { S += red[j]; P += red[16 + j]; }
            const float woy = __fdividef(P, S);
            float ctx = 0.f;
            #pragma unroll
            for (int j = 0; j < 8; j++) ctx += part[(j << 6) + tid];
            float pred = woy + xo + __fdividef(ctx, esum) + bo_r;
            out[(size_t)(b * TT + t) * OO + o_base + tid] = pred;
            #pragma unroll
            for (int r = 0; r < CPG; r++) dsm_st(pr_raddr[r], pred);
            asm volatile("bar.sync 2, 64;" ::: "memory");
            if (tid < CPG) mbar_arrive_remote(barB_r);
        }
        mbar_wait(barB_l, par);                    // pred_s complete
    }
}

// =======================================================================
// launch
// =======================================================================
extern "C" void kernel_launch(void* const* d_in, const int* in_sizes, int n_in,
                              void* d_out, int out_size)
{
    const float* inputs = (const float*)d_in[0];
    const float* Wa     = (const float*)d_in[1];
    const float* Ua     = (const float*)d_in[2];
    const float* Va     = (const float*)d_in[3];
    const float* Ba     = (const float*)d_in[4];
    const float* Wo     = (const float*)d_in[5];
    const float* Uo     = (const float*)d_in[6];
    const float* Co     = (const float*)d_in[7];
    const float* Bo     = (const float*)d_in[8];
    const float* emb    = (const float*)d_in[9];
    float* out = (float*)d_out;

    dim3 g(16, 8, 3);
    gemm3_kernel<<<g, 256>>>(inputs, Ua, Co, Uo, Ba);
    embwo_kernel<<<64, 256>>>(emb, Wo);

    cudaFuncSetAttribute(scan_kernel,
                         cudaFuncAttributeMaxDynamicSharedMemorySize, SMEM_BYTES);
    scan_kernel<<<BB * CPG, NTH, SMEM_BYTES>>>(Wa, Va, Bo, out);
}

// round 6
// speedup vs baseline: 1.3275x; 1.3275x over previous
#include <cuda_runtime.h>
#include <cstdint>

#define BB 8
#define TT 128
#define DD 512
#define OO 512
#define CPG 8              // CTAs per cluster (one cluster per batch)
#define OSL (OO/CPG)       // 64  output-col slice per CTA
#define NTH 256
#define FULLMASK 0xffffffffu

// ---------------- device scratch (no allocations allowed) ----------------
__device__ float g_UaH[BB*TT*OO];   // inputs@Ua + Ba
__device__ float g_IC [BB*TT*OO];   // inputs@Co
__device__ float g_XUo[BB*TT*OO];   // inputs@Uo
__device__ float g_embWo[OO];       // emb@Wo

// ---------------- helpers ----------------
__device__ __forceinline__ float wredsum(float v) {
    #pragma unroll
    for (int s = 16; s; s >>= 1) v += __shfl_xor_sync(FULLMASK, v, s);
    return v;
}
__device__ __forceinline__ float tanhapx(float x) {
    float y;
    asm("tanh.approx.f32 %0, %1;" : "=f"(y) : "f"(x));
    return y;
}
__device__ __forceinline__ uint32_t smem_u32(const void* p) {
    uint32_t a;
    asm("{ .reg .u64 t; cvta.to.shared.u64 t, %1; cvt.u32.u64 %0, t; }"
        : "=r"(a) : "l"(p));
    return a;
}
__device__ __forceinline__ uint32_t dsm_map(uint32_t laddr, uint32_t rank) {
    uint32_t r;
    asm("mapa.shared::cluster.u32 %0, %1, %2;" : "=r"(r) : "r"(laddr), "r"(rank));
    return r;
}
__device__ __forceinline__ void dsm_st(uint32_t raddr, float v) {
    asm volatile("st.shared::cluster.f32 [%0], %1;" :: "r"(raddr), "f"(v) : "memory");
}
#define CLUSTER_SYNC() do { \
    asm volatile("barrier.cluster.arrive.aligned;" ::: "memory"); \
    asm volatile("barrier.cluster.wait.aligned;"   ::: "memory"); \
} while (0)

// packed fp32x2 fma: d += a*b (two fp32 lanes). Used ONLY with register /
// broadcast-LDS operands (GEMM f32x2 experiment regressed: conflicted LDS).
__device__ __forceinline__ void fma2(unsigned long long& d,
                                     unsigned long long a, unsigned long long b) {
    asm("fma.rn.f32x2 %0, %1, %2, %0;" : "+l"(d) : "l"(a), "l"(b));
}
__device__ __forceinline__ unsigned long long pack2(float x, float y) {
    unsigned long long r;
    asm("mov.b64 %0, {%1, %2};" : "=l"(r) : "f"(x), "f"(y));
    return r;
}
__device__ __forceinline__ float2 unpack2(unsigned long long v) {
    float2 r;
    asm("mov.b64 {%0, %1}, %2;" : "=f"(r.x), "=f"(r.y) : "l"(v));
    return r;
}

// =======================================================================
// GEMM (R3 structure + register prefetch): C_z = A[1024x512] @ B_z[512x512]
// z=0:Ua(+Ba), 1:Co, 2:Uo.  64x64 tile, BK=16, 256 threads, 4x4/thread.
// =======================================================================
__global__ __launch_bounds__(256) void gemm3_kernel(
    const float* __restrict__ A,
    const float* __restrict__ Ua,
    const float* __restrict__ Co,
    const float* __restrict__ Uo,
    const float* __restrict__ Ba)
{
    __shared__ float As[16][64];   // k-major
    __shared__ float Bs[16][64];

    const int m0 = blockIdx.x * 64;
    const int n0 = blockIdx.y * 64;
    const int z  = blockIdx.z;
    const float* __restrict__ Bm = (z == 0) ? Ua : ((z == 1) ? Co : Uo);
    float* Cout = (z == 0) ? g_UaH : ((z == 1) ? g_IC : g_XUo);

    const int tid  = threadIdx.x;
    const int tx   = tid & 15;
    const int ty   = tid >> 4;
    const int la_m = tid >> 2;
    const int la_k = (tid & 3) << 2;
    const int lb_k = tid >> 4;
    const int lb_n = (tid & 15) << 2;

    float acc[4][4];
    #pragma unroll
    for (int i = 0; i < 4; i++)
        #pragma unroll
        for (int j = 0; j < 4; j++) acc[i][j] = 0.f;

    // prefetch first k-tile
    float4 av = *(const float4*)&A [(m0 + la_m) * DD + la_k];
    float4 bv = *(const float4*)&Bm[lb_k * OO + n0 + lb_n];

    for (int k0 = 0; k0 < DD; k0 += 16) {
        __syncthreads();                 // previous compute done
        As[la_k + 0][la_m] = av.x;
        As[la_k + 1][la_m] = av.y;
        As[la_k + 2][la_m] = av.z;
        As[la_k + 3][la_m] = av.w;
        *(float4*)&Bs[lb_k][lb_n] = bv;
        __syncthreads();
        if (k0 + 16 < DD) {              // prefetch next tile (hidden by compute)
            av = *(const float4*)&A [(m0 + la_m) * DD + (k0 + 16) + la_k];
            bv = *(const float4*)&Bm[(k0 + 16 + lb_k) * OO + n0 + lb_n];
        }
        #pragma unroll
        for (int kk = 0; kk < 16; kk++) {
            float4 a = *(const float4*)&As[kk][ty << 2];
            float4 b = *(const float4*)&Bs[kk][tx << 2];
            acc[0][0] += a.x * b.x; acc[0][1] += a.x * b.y; acc[0][2] += a.x * b.z; acc[0][3] += a.x * b.w;
            acc[1][0] += a.y * b.x; acc[1][1] += a.y * b.y; acc[1][2] += a.y * b.z; acc[1][3] += a.y * b.w;
            acc[2][0] += a.z * b.x; acc[2][1] += a.z * b.y; acc[2][2] += a.z * b.z; acc[2][3] += a.z * b.w;
            acc[3][0] += a.w * b.x; acc[3][1] += a.w * b.y; acc[3][2] += a.w * b.z; acc[3][3] += a.w * b.w;
        }
    }
    #pragma unroll
    for (int i = 0; i < 4; i++) {
        int r = m0 + (ty << 2) + i;
        #pragma unroll
        for (int j = 0; j < 4; j++) {
            int c = n0 + (tx << 2) + j;
            float v = acc[i][j];
            if (z == 0) v += Ba[c];
            Cout[(size_t)r * OO + c] = v;
        }
    }
}

// =======================================================================
// embWo[i] = sum_j emb[i][j] * Wo[j]   (one warp per row)
// =======================================================================
__global__ __launch_bounds__(256) void embwo_kernel(
    const float* __restrict__ emb, const float* __restrict__ Wo)
{
    const int row  = (blockIdx.x << 3) + (threadIdx.x >> 5);
    const int lane = threadIdx.x & 31;
    const float* rp = emb + row * OO;
    float acc = 0.f;
    #pragma unroll 4
    for (int j = lane; j < OO; j += 32) acc += rp[j] * Wo[j];
    acc = wredsum(acc);
    if (lane == 0) g_embWo[row] = acc;
}

// =======================================================================
// Persistent clustered scan (R4 structure: 256 thr, 2x barrier.cluster).
// New: UaH pitch-68 float4 path, Va in regs, fma2 WaS, float4 wbuf in ctx.
// =======================================================================
#define UAH_PITCH 68
// shared memory layout (float offsets; all float4-aligned)
#define UAH_OFF   0                            // [128][68] = 8704
#define IC_OFF    (UAH_OFF + TT*UAH_PITCH)     // [128][64] = 8192
#define PRED_OFF  (IC_OFF + TT*OSL)            // [512] broadcast target
#define SIG_OFF   (PRED_OFF + OO)              // [512]
#define SPART_OFF (SIG_OFF + OO)               // [8][128] broadcast target
#define WBUF_OFF  (SPART_OFF + CPG*TT)         // [128]
#define WAS_OFF   (WBUF_OFF + TT)              // [64]
#define RED_OFF   (WAS_OFF + OSL)              // [32]
#define PART_OFF  (RED_OFF + 32)               // [256]
#define SMEM_FLOATS (PART_OFF + 256)
#define SMEM_BYTES  (SMEM_FLOATS * 4)

__global__ __launch_bounds__(NTH, 1) __cluster_dims__(CPG, 1, 1)
void scan_kernel(const float* __restrict__ Wa,
                 const float* __restrict__ Va,
                 const float* __restrict__ Bo,
                 float* __restrict__ out)
{
    extern __shared__ float sm[];
    float* UaH_s  = sm + UAH_OFF;
    float* IC_s   = sm + IC_OFF;
    float* pred_s = sm + PRED_OFF;
    float* sig_s  = sm + SIG_OFF;
    float* spart  = sm + SPART_OFF;
    float* wbuf   = sm + WBUF_OFF;
    float* WaS_s  = sm + WAS_OFF;
    float* red    = sm + RED_OFF;
    float* part   = sm + PART_OFF;

    const uint32_t sbase = smem_u32(sm);

    const int tid  = threadIdx.x;
    const int lane = tid & 31;
    const int wid  = tid >> 5;
    const int b    = blockIdx.x >> 3;     // batch
    const int crk  = blockIdx.x & 7;      // cluster rank
    const int o_base = crk * OSL;
    const int oc = tid & 63;              // o within slice (P1 WaS / P3 ctx)
    const int kc = tid >> 6;              // quarter split  (P1 WaS / P3 ctx)
    const int ts = tid & 127;             // timestep       (P2)
    const int q  = tid >> 7;              // o half         (P2)

    // ---------------- prologue ----------------
    for (int i = tid; i < TT * OSL; i += NTH) {
        int tt = i >> 6, o = i & 63;
        float v = g_UaH[(size_t)(b * TT + tt) * OO + o_base + o];
        UaH_s[tt * UAH_PITCH + o] = v;
        IC_s[(tt << 6) + o]       = g_IC[(size_t)(b * TT + tt) * OO + o_base + o];
    }
    for (int i = tid; i < OO; i += NTH) pred_s[i] = 0.f;

    // Wa slice packed in registers: thread (oc,kc) holds k in [kc*128, kc*128+128)
    // wreg2[j] = (Wa[kc*128+2j][col], Wa[kc*128+2j+1][col])
    unsigned long long wreg2[64];
    {
        const int col = o_base + oc;
        #pragma unroll
        for (int j = 0; j < 64; j++) {
            float w0 = Wa[(size_t)(kc * 128 + 2 * j)     * OO + col];
            float w1 = Wa[(size_t)(kc * 128 + 2 * j + 1) * OO + col];
            wreg2[j] = pack2(w0, w1);
        }
    }
    // Va slice for P2 in registers (o = o_base + q*32 + j)
    float va_r[32];
    #pragma unroll
    for (int j = 0; j < 32; j++) va_r[j] = Va[o_base + (q << 5) + j];

    const float ew0  = g_embWo[tid];
    const float ew1  = g_embWo[tid + 256];
    const float bo_r = (tid < OSL) ? Bo[o_base + tid] : 0.f;

    // loop-invariant remote addresses
    uint32_t sc_raddr[CPG];    // spart[crk][ts]     (used by tid<128)
    uint32_t pr_raddr[CPG];    // pred_s[o_base+oc]  (used by tid<64)
    {
        uint32_t a1 = sbase + (uint32_t)(SPART_OFF + crk * TT + ts) * 4u;
        uint32_t a2 = sbase + (uint32_t)(PRED_OFF + o_base + oc) * 4u;
        #pragma unroll
        for (int r = 0; r < CPG; r++) {
            sc_raddr[r] = dsm_map(a1, r);
            pr_raddr[r] = dsm_map(a2, r);
        }
    }
    __syncthreads();

    // ---------------- scan over T steps ----------------
    for (int t = 0; t < TT; t++) {
        // prefetch XUo[b, (t-1) mod T, own o-slice]
        float xo = 0.f;
        if (tid < OSL)
            xo = __ldg(&g_XUo[(size_t)(b * TT + ((t + TT - 1) & (TT - 1))) * OO + o_base + tid]);

        // ============ P1: exp/sigmoid + woy partials + WaS ============
        float pv0 = pred_s[tid];
        float pv1 = pred_s[tid + 256];
        float e0 = __expf(pv0), e1 = __expf(pv1);        // |pred| small: no max-sub
        sig_s[tid]       = __fdividef(1.f, 1.f + __expf(-pv0));
        sig_s[tid + 256] = __fdividef(1.f, 1.f + __expf(-pv1));
        float ps = wredsum(e0 + e1);
        float pd = wredsum(e0 * ew0 + e1 * ew1);
        if (lane == 0) { red[wid] = ps; red[8 + wid] = pd; }
        __syncthreads();                                  // (1) red + sig_s ready

        float S = 0.f, P = 0.f;
        #pragma unroll
        for (int i = 0; i < 8; i++) { S += red[i]; P += red[8 + i]; }
        const float woy = __fdividef(P, S);

        // WaS partial via fp32x2: thread (oc,kc) covers k in [kc*128,kc*128+128)
        {
            const ulonglong2* sp2 = (const ulonglong2*)(sig_s + (kc << 7));
            unsigned long long acc2 = 0ull;
            #pragma unroll
            for (int i = 0; i < 32; i++) {
                ulonglong2 sv = sp2[i];                   // broadcast LDS.128
                fma2(acc2, sv.x, wreg2[2 * i]);
                fma2(acc2, sv.y, wreg2[2 * i + 1]);
            }
            float2 f = unpack2(acc2);
            part[tid] = f.x + f.y;
        }
        __syncthreads();                                  // (2)
        if (tid < OSL)
            WaS_s[tid] = part[tid] + part[64 + tid] + part[128 + tid] + part[192 + tid];
        __syncthreads();                                  // (3) WaS_s ready

        // ============ P2: partial scores, all t, own o-half (float4 path) ============
        {
            const float* urow = UaH_s + ts * UAH_PITCH + (q << 5);
            const float* wp   = WaS_s + (q << 5);
            float acc = 0.f;
            #pragma unroll
            for (int j = 0; j < 8; j++) {
                float4 u = *(const float4*)&urow[j << 2]; // conflict-free (pitch 68)
                float4 w = *(const float4*)&wp[j << 2];   // broadcast
                acc += tanhapx(u.x + w.x) * va_r[(j << 2) + 0]
                     + tanhapx(u.y + w.y) * va_r[(j << 2) + 1]
                     + tanhapx(u.z + w.z) * va_r[(j << 2) + 2]
                     + tanhapx(u.w + w.w) * va_r[(j << 2) + 3];
            }
            part[(q << 7) + ts] = acc;
        }
        __syncthreads();                                  // (4)
        if (tid < TT) {
            float s = part[tid] + part[128 + tid];
            #pragma unroll
            for (int r = 0; r < CPG; r++) dsm_st(sc_raddr[r], s);
        }
        CLUSTER_SYNC();                                   // sync#1: spart complete

        // ============ P3: softmax over T + ctx + pred ============
        float esv = 0.f;
        if (tid < TT) {
            float sc = 0.f;
            #pragma unroll
            for (int r = 0; r < CPG; r++) sc += spart[(r << 7) + tid];
            esv = __expf(sc);                             // |score| small: no max-sub
            wbuf[tid] = esv;
        }
        float sp = wredsum(esv);                          // warps 4..7 add 0
        if (lane == 0) red[16 + wid] = sp;
        __syncthreads();                                  // (5) wbuf + red ready
        const float esum = (red[16] + red[17]) + (red[18] + red[19]);

        // ctx partial: thread (oc,kc) covers t' in [kc*32, kc*32+32)
        {
            float acc = 0.f;
            const int base = kc << 5;
            #pragma unroll
            for (int j = 0; j < 8; j++) {
                float4 wb = *(const float4*)&wbuf[base + (j << 2)];  // broadcast
                acc += wb.x * IC_s[((base + (j << 2) + 0) << 6) + oc]
                     + wb.y * IC_s[((base + (j << 2) + 1) << 6) + oc]
                     + wb.z * IC_s[((base + (j << 2) + 2) << 6) + oc]
                     + wb.w * IC_s[((base + (j << 2) + 3) << 6) + oc];
            }
            part[tid] = acc;
        }
        __syncthreads();                                  // (6)
        if (tid < OSL) {
            float ctx  = part[tid] + part[64 + tid] + part[128 + tid] + part[192 + tid];
            float pred = woy + xo + __fdividef(ctx, esum) + bo_r;
            out[(size_t)(b * TT + t) * OO + o_base + tid] = pred;
            #pragma unroll
            for (int r = 0; r < CPG; r++) dsm_st(pr_raddr[r], pred);
        }
        CLUSTER_SYNC();                                   // sync#2: pred_s complete
    }
}

// =======================================================================
// launch
// =======================================================================
extern "C" void kernel_launch(void* const* d_in, const int* in_sizes, int n_in,
                              void* d_out, int out_size)
{
    const float* inputs = (const float*)d_in[0];
    const float* Wa     = (const float*)d_in[1];
    const float* Ua     = (const float*)d_in[2];
    const float* Va     = (const float*)d_in[3];
    const float* Ba     = (const float*)d_in[4];
    const float* Wo     = (const float*)d_in[5];
    const float* Uo     = (const float*)d_in[6];
    const float* Co     = (const float*)d_in[7];
    const float* Bo     = (const float*)d_in[8];
    const float* emb    = (const float*)d_in[9];
    float* out = (float*)d_out;

    dim3 g(16, 8, 3);
    gemm3_kernel<<<g, 256>>>(inputs, Ua, Co, Uo, Ba);
    embwo_kernel<<<64, 256>>>(emb, Wo);

    cudaFuncSetAttribute(scan_kernel,
                         cudaFuncAttributeMaxDynamicSharedMemorySize, SMEM_BYTES);
    scan_kernel<<<BB * CPG, NTH, SMEM_BYTES>>>(Wa, Va, Bo, out);
}

// round 7
// speedup vs baseline: 1.5799x; 1.1901x over previous
#include <cuda_runtime.h>
#include <cstdint>

#define BB 8
#define TT 128
#define DD 512
#define OO 512
#define CPG 8              // CTAs per cluster (one cluster per batch)
#define OSL (OO/CPG)       // 64  output-col slice per CTA
#define NTH 256
#define FULLMASK 0xffffffffu

// ---------------- device scratch (no allocations allowed) ----------------
__device__ float g_UaH[BB*TT*OO];   // inputs@Ua + Ba
__device__ float g_IC [BB*TT*OO];   // inputs@Co
__device__ float g_XUo[BB*TT*OO];   // inputs@Uo
__device__ float g_embWo[OO];       // emb@Wo

// ---------------- helpers ----------------
__device__ __forceinline__ float wredsum(float v) {
    #pragma unroll
    for (int s = 16; s; s >>= 1) v += __shfl_xor_sync(FULLMASK, v, s);
    return v;
}
__device__ __forceinline__ float tanhapx(float x) {
    float y;
    asm("tanh.approx.f32 %0, %1;" : "=f"(y) : "f"(x));
    return y;
}
__device__ __forceinline__ uint32_t smem_u32(const void* p) {
    uint32_t a;
    asm("{ .reg .u64 t; cvta.to.shared.u64 t, %1; cvt.u32.u64 %0, t; }"
        : "=r"(a) : "l"(p));
    return a;
}
__device__ __forceinline__ uint32_t dsm_map(uint32_t laddr, uint32_t rank) {
    uint32_t r;
    asm("mapa.shared::cluster.u32 %0, %1, %2;" : "=r"(r) : "r"(laddr), "r"(rank));
    return r;
}
__device__ __forceinline__ void mbar_init(uint32_t a, uint32_t cnt) {
    asm volatile("mbarrier.init.shared.b64 [%0], %1;" :: "r"(a), "r"(cnt) : "memory");
}
__device__ __forceinline__ void mbar_arm(uint32_t a, uint32_t tx) {
    asm volatile("mbarrier.arrive.expect_tx.shared.b64 _, [%0], %1;"
                 :: "r"(a), "r"(tx) : "memory");
}
__device__ __forceinline__ void mbar_wait(uint32_t a, uint32_t parity) {
    asm volatile(
        "{\n\t.reg .pred P;\n\t"
        "W_%=:\n\t"
        "mbarrier.try_wait.parity.acquire.cluster.shared::cta.b64 P, [%0], %1, 0x989680;\n\t"
        "@!P bra W_%=;\n\t}"
        :: "r"(a), "r"(parity) : "memory");
}
// fire-and-forget remote store, completion counted on remote mbarrier (bytes)
__device__ __forceinline__ void st_async(uint32_t raddr, float v, uint32_t rbar) {
    asm volatile(
        "st.async.shared::cluster.mbarrier::complete_tx::bytes.b32 [%0], %1, [%2];"
        :: "r"(raddr), "r"(__float_as_uint(v)), "r"(rbar) : "memory");
}
#define CLUSTER_SYNC() do { \
    asm volatile("barrier.cluster.arrive.aligned;" ::: "memory"); \
    asm volatile("barrier.cluster.wait.aligned;"   ::: "memory"); \
} while (0)

// packed fp32x2 fma (register/broadcast-LDS operands only)
__device__ __forceinline__ void fma2(unsigned long long& d,
                                     unsigned long long a, unsigned long long b) {
    asm("fma.rn.f32x2 %0, %1, %2, %0;" : "+l"(d) : "l"(a), "l"(b));
}
__device__ __forceinline__ unsigned long long pack2(float x, float y) {
    unsigned long long r;
    asm("mov.b64 %0, {%1, %2};" : "=l"(r) : "f"(x), "f"(y));
    return r;
}
__device__ __forceinline__ float2 unpack2(unsigned long long v) {
    float2 r;
    asm("mov.b64 {%0, %1}, %2;" : "=f"(r.x), "=f"(r.y) : "l"(v));
    return r;
}

// =======================================================================
// GEMM (unchanged from R6, 58.4us): C_z = A[1024x512] @ B_z[512x512]
// =======================================================================
__global__ __launch_bounds__(256) void gemm3_kernel(
    const float* __restrict__ A,
    const float* __restrict__ Ua,
    const float* __restrict__ Co,
    const float* __restrict__ Uo,
    const float* __restrict__ Ba)
{
    __shared__ float As[16][64];   // k-major
    __shared__ float Bs[16][64];

    const int m0 = blockIdx.x * 64;
    const int n0 = blockIdx.y * 64;
    const int z  = blockIdx.z;
    const float* __restrict__ Bm = (z == 0) ? Ua : ((z == 1) ? Co : Uo);
    float* Cout = (z == 0) ? g_UaH : ((z == 1) ? g_IC : g_XUo);

    const int tid  = threadIdx.x;
    const int tx   = tid & 15;
    const int ty   = tid >> 4;
    const int la_m = tid >> 2;
    const int la_k = (tid & 3) << 2;
    const int lb_k = tid >> 4;
    const int lb_n = (tid & 15) << 2;

    float acc[4][4];
    #pragma unroll
    for (int i = 0; i < 4; i++)
        #pragma unroll
        for (int j = 0; j < 4; j++) acc[i][j] = 0.f;

    float4 av = *(const float4*)&A [(m0 + la_m) * DD + la_k];
    float4 bv = *(const float4*)&Bm[lb_k * OO + n0 + lb_n];

    for (int k0 = 0; k0 < DD; k0 += 16) {
        __syncthreads();
        As[la_k + 0][la_m] = av.x;
        As[la_k + 1][la_m] = av.y;
        As[la_k + 2][la_m] = av.z;
        As[la_k + 3][la_m] = av.w;
        *(float4*)&Bs[lb_k][lb_n] = bv;
        __syncthreads();
        if (k0 + 16 < DD) {
            av = *(const float4*)&A [(m0 + la_m) * DD + (k0 + 16) + la_k];
            bv = *(const float4*)&Bm[(k0 + 16 + lb_k) * OO + n0 + lb_n];
        }
        #pragma unroll
        for (int kk = 0; kk < 16; kk++) {
            float4 a = *(const float4*)&As[kk][ty << 2];
            float4 b = *(const float4*)&Bs[kk][tx << 2];
            acc[0][0] += a.x * b.x; acc[0][1] += a.x * b.y; acc[0][2] += a.x * b.z; acc[0][3] += a.x * b.w;
            acc[1][0] += a.y * b.x; acc[1][1] += a.y * b.y; acc[1][2] += a.y * b.z; acc[1][3] += a.y * b.w;
            acc[2][0] += a.z * b.x; acc[2][1] += a.z * b.y; acc[2][2] += a.z * b.z; acc[2][3] += a.z * b.w;
            acc[3][0] += a.w * b.x; acc[3][1] += a.w * b.y; acc[3][2] += a.w * b.z; acc[3][3] += a.w * b.w;
        }
    }
    #pragma unroll
    for (int i = 0; i < 4; i++) {
        int r = m0 + (ty << 2) + i;
        #pragma unroll
        for (int j = 0; j < 4; j++) {
            int c = n0 + (tx << 2) + j;
            float v = acc[i][j];
            if (z == 0) v += Ba[c];
            Cout[(size_t)r * OO + c] = v;
        }
    }
}

// =======================================================================
// embWo[i] = sum_j emb[i][j] * Wo[j]
// =======================================================================
__global__ __launch_bounds__(256) void embwo_kernel(
    const float* __restrict__ emb, const float* __restrict__ Wo)
{
    const int row  = (blockIdx.x << 3) + (threadIdx.x >> 5);
    const int lane = threadIdx.x & 31;
    const float* rp = emb + row * OO;
    float acc = 0.f;
    #pragma unroll 4
    for (int j = lane; j < OO; j += 32) acc += rp[j] * Wo[j];
    acc = wredsum(acc);
    if (lane == 0) g_embWo[row] = acc;
}

// =======================================================================
// Persistent clustered scan: st.async + tx-counting mbarriers, no
// in-loop barrier.cluster. Double-buffered exchanges, 2 waits/step.
// =======================================================================
#define UAH_PITCH 68
#define SG_PITCH  68        // 64 sig + 4 scalar slots per rank
// shared memory layout (float offsets)
#define UAH_OFF   0                              // [128][68] = 8704
#define IC_OFF    (UAH_OFF + TT*UAH_PITCH)       // [128][64] = 8192
#define SG_OFF    (IC_OFF + TT*OSL)              // 2 x [8][68] = 1088
#define SPART_OFF (SG_OFF + 2*CPG*SG_PITCH)      // 2 x [8][128] = 2048
#define WAS_OFF   (SPART_OFF + 2*CPG*TT)         // [64]
#define WBUF_OFF  (WAS_OFF + OSL)                // [128]
#define RED_OFF   (WBUF_OFF + TT)                // [32]
#define PARTA_OFF (RED_OFF + 32)                 // [256]  (WaS partials only)
#define PARTB_OFF (PARTA_OFF + 256)              // [256]  (P2 scores / P3 ctx)
#define BAR_OFF   (PARTB_OFF + 256)              // 4 x u64 (score0,score1,sig0,sig1)
#define SMEM_FLOATS (BAR_OFF + 8)
#define SMEM_BYTES  (SMEM_FLOATS * 4)

#define TX_SCORE (CPG*TT*4)          // 4096 bytes/phase
#define TX_SIG   (CPG*(OSL+4)*4)     // 2176 bytes/phase

__global__ __launch_bounds__(NTH, 1) __cluster_dims__(CPG, 1, 1)
void scan_kernel(const float* __restrict__ Wa,
                 const float* __restrict__ Va,
                 const float* __restrict__ Bo,
                 float* __restrict__ out)
{
    extern __shared__ float sm[];
    float* UaH_s = sm + UAH_OFF;
    float* IC_s  = sm + IC_OFF;
    float* wbuf  = sm + WBUF_OFF;
    float* WaS_s = sm + WAS_OFF;
    float* red   = sm + RED_OFF;
    float* partA = sm + PARTA_OFF;
    float* partB = sm + PARTB_OFF;

    const uint32_t sbase = smem_u32(sm);
    // local mbarrier byte addresses: score[0],score[1],sig[0],sig[1]
    const uint32_t barbase = sbase + BAR_OFF * 4;

    const int tid  = threadIdx.x;
    const int lane = tid & 31;
    const int wid  = tid >> 5;
    const int b    = blockIdx.x >> 3;     // batch
    const int crk  = blockIdx.x & 7;      // cluster rank
    const int o_base = crk * OSL;
    const int oc = tid & 63;
    const int kc = tid >> 6;              // 0..3
    const int ts = tid & 127;
    const int q  = tid >> 7;              // 0..1

    // ---------------- prologue ----------------
    for (int i = tid; i < TT * OSL; i += NTH) {
        int tt = i >> 6, o = i & 63;
        UaH_s[tt * UAH_PITCH + o] = g_UaH[(size_t)(b * TT + tt) * OO + o_base + o];
        IC_s[(tt << 6) + o]       = g_IC [(size_t)(b * TT + tt) * OO + o_base + o];
    }

    // Wa slice packed: thread (oc,kc) holds k in [kc*128, kc*128+128)
    unsigned long long wreg2[64];
    {
        const int col = o_base + oc;
        #pragma unroll
        for (int j = 0; j < 64; j++) {
            float w0 = Wa[(size_t)(kc * 128 + 2 * j)     * OO + col];
            float w1 = Wa[(size_t)(kc * 128 + 2 * j + 1) * OO + col];
            wreg2[j] = pack2(w0, w1);
        }
    }
    float va_r[32];
    #pragma unroll
    for (int j = 0; j < 32; j++) va_r[j] = Va[o_base + (q << 5) + j];

    const float ew0   = g_embWo[tid];
    const float ew1   = g_embWo[tid + 256];
    const float ew_sl = g_embWo[o_base + oc];            // own-slice embWo
    const float bo_r  = (tid < OSL) ? Bo[o_base + tid] : 0.f;

    // remote shared-window bases (rank in high bits; offsets add linearly)
    uint32_t rbase[CPG];
    #pragma unroll
    for (int r = 0; r < CPG; r++) rbase[r] = dsm_map(sbase, r);

    // init + arm barriers (phase 0)
    if (tid == 0) {
        #pragma unroll
        for (int i = 0; i < 4; i++) mbar_init(barbase + i * 8, 1);
        mbar_arm(barbase + 0,  TX_SCORE);
        mbar_arm(barbase + 8,  TX_SCORE);
        mbar_arm(barbase + 16, TX_SIG);
        mbar_arm(barbase + 24, TX_SIG);
    }

    // t=0 seed: sig(-1)=0.5, S=512, P=sum(embWo). Fill local sgbuf[1].
    float p0p = wredsum(ew0 + ew1);
    if (lane == 0) red[wid] = p0p;
    {
        float* sg1 = sm + SG_OFF + CPG * SG_PITCH;   // buffer 1
        for (int i = tid; i < CPG * SG_PITCH; i += NTH)
            sg1[i] = ((i % SG_PITCH) < OSL) ? 0.5f : 0.f;
    }
    __syncthreads();
    if (tid == 0) {
        float P0 = 0.f;
        #pragma unroll
        for (int i = 0; i < 8; i++) P0 += red[i];
        float* sg1 = sm + SG_OFF + CPG * SG_PITCH;
        sg1[OSL + 0] = 512.f;   // S partial (rank0/w0 slot)
        sg1[OSL + 2] = P0;      // P partial
    }
    __syncthreads();
    CLUSTER_SYNC();   // all CTAs: barriers initialized+armed before any st.async

    // ---------------- scan over T steps ----------------
    for (int t = 0; t < TT; t++) {
        const int buf = t & 1;

        // prefetch XUo[b, (t-1) mod T, own o-slice]
        float xo = 0.f;
        if (tid < OSL)
            xo = __ldg(&g_XUo[(size_t)(b * TT + ((t + TT - 1) & (TT - 1))) * OO + o_base + tid]);

        // -------- wait for sig/scalars of pred(t-1) --------
        const uint32_t sigbar_l = barbase + 16 + (buf ^ 1) * 8;
        if (t > 0) {
            mbar_wait(sigbar_l, ((t - 1) >> 1) & 1);
            if (tid == 0) mbar_arm(sigbar_l, TX_SIG);   // re-arm for t+2 usage
        }
        const float* sgc = sm + SG_OFF + (buf ^ 1) * (CPG * SG_PITCH);

        // scalars -> woy
        float S = 0.f, P = 0.f;
        #pragma unroll
        for (int r = 0; r < CPG; r++) {
            const float* sr = sgc + r * SG_PITCH + OSL;
            S += sr[0] + sr[1];
            P += sr[2] + sr[3];
        }
        const float woy = __fdividef(P, S);

        // -------- WaS partial (fp32x2, reg weights, broadcast sig) --------
        {
            unsigned long long acc2 = 0ull;
            #pragma unroll
            for (int rr = 0; rr < 2; rr++) {
                const ulonglong2* sp2 =
                    (const ulonglong2*)(sgc + (2 * kc + rr) * SG_PITCH);
                #pragma unroll
                for (int i = 0; i < 16; i++) {
                    ulonglong2 sv = sp2[i];
                    fma2(acc2, sv.x, wreg2[rr * 32 + 2 * i]);
                    fma2(acc2, sv.y, wreg2[rr * 32 + 2 * i + 1]);
                }
            }
            float2 f = unpack2(acc2);
            partA[tid] = f.x + f.y;
        }
        __syncthreads();                                   // s1
        if (tid < OSL)
            WaS_s[tid] = partA[tid] + partA[64 + tid] + partA[128 + tid] + partA[192 + tid];
        __syncthreads();                                   // s2

        // -------- P2: partial scores, all t, own o-half --------
        {
            const float* urow = UaH_s + ts * UAH_PITCH + (q << 5);
            const float* wp   = WaS_s + (q << 5);
            float acc = 0.f;
            #pragma unroll
            for (int j = 0; j < 8; j++) {
                float4 u = *(const float4*)&urow[j << 2];
                float4 w = *(const float4*)&wp[j << 2];
                acc += tanhapx(u.x + w.x) * va_r[(j << 2) + 0]
                     + tanhapx(u.y + w.y) * va_r[(j << 2) + 1]
                     + tanhapx(u.z + w.z) * va_r[(j << 2) + 2]
                     + tanhapx(u.w + w.w) * va_r[(j << 2) + 3];
            }
            partB[(q << 7) + ts] = acc;
        }
        __syncthreads();                                   // s3
        if (tid < TT) {
            float s = partB[tid] + partB[128 + tid];
            const uint32_t doff = (uint32_t)(SPART_OFF + buf * (CPG * TT) + crk * TT + tid) * 4u;
            const uint32_t boff = (uint32_t)(BAR_OFF * 4 + buf * 8);
            #pragma unroll
            for (int r = 0; r < CPG; r++)
                st_async(rbase[r] + doff, s, rbase[r] + boff);
        }

        // -------- wait for all score partials --------
        const uint32_t scorebar_l = barbase + buf * 8;
        mbar_wait(scorebar_l, (t >> 1) & 1);
        if (tid == 0) mbar_arm(scorebar_l, TX_SCORE);      // re-arm for t+2

        // -------- P3: softmax over T + ctx + pred + sig broadcast --------
        const float* sp = sm + SPART_OFF + buf * (CPG * TT);
        if (tid < TT) {
            float sc = 0.f;
            #pragma unroll
            for (int r = 0; r < CPG; r++) sc += sp[(r << 7) + tid];
            float esv = __expf(sc);                        // |score| small: no max-sub
            wbuf[tid] = esv;
            float spp = wredsum(esv);
            if (lane == 0) red[wid] = spp;                 // wid 0..3
        }
        __syncthreads();                                   // s4
        const float esum = (red[0] + red[1]) + (red[2] + red[3]);

        // ctx partial: thread (oc,kc) covers t' in [kc*32, kc*32+32)
        {
            float acc = 0.f;
            const int base = kc << 5;
            #pragma unroll
            for (int j = 0; j < 8; j++) {
                float4 wb = *(const float4*)&wbuf[base + (j << 2)];
                acc += wb.x * IC_s[((base + (j << 2) + 0) << 6) + oc]
                     + wb.y * IC_s[((base + (j << 2) + 1) << 6) + oc]
                     + wb.z * IC_s[((base + (j << 2) + 2) << 6) + oc]
                     + wb.w * IC_s[((base + (j << 2) + 3) << 6) + oc];
            }
            partB[tid] = acc;
        }
        __syncthreads();                                   // s5
        if (tid < OSL) {
            float ctx  = partB[tid] + partB[64 + tid] + partB[128 + tid] + partB[192 + tid];
            float pred = woy + xo + __fdividef(ctx, esum) + bo_r;
            out[(size_t)(b * TT + t) * OO + o_base + tid] = pred;

            // fold old-P1 here: sigmoid + exp partials of pred(t), broadcast
            float e   = __expf(pred);
            float sg  = __fdividef(1.f, 1.f + __expf(-pred));
            float pe  = wredsum(e);            // warp-local (tids 0-31 / 32-63)
            float pp  = wredsum(e * ew_sl);
            if (t < TT - 1) {
                const uint32_t sgoff =
                    (uint32_t)(SG_OFF + buf * (CPG * SG_PITCH) + crk * SG_PITCH + tid) * 4u;
                const uint32_t sboff = (uint32_t)(BAR_OFF * 4 + 16 + buf * 8);
                #pragma unroll
                for (int r = 0; r < CPG; r++)
                    st_async(rbase[r] + sgoff, sg, rbase[r] + sboff);
                if (lane == 0) {
                    const int w = tid >> 5;    // 0 or 1
                    const uint32_t so =
                        (uint32_t)(SG_OFF + buf * (CPG * SG_PITCH) + crk * SG_PITCH + OSL + w) * 4u;
                    const uint32_t po = so + 8u;   // slots 66/67 = 64/65 + 2
                    #pragma unroll
                    for (int r = 0; r < CPG; r++) {
                        st_async(rbase[r] + so, pe, rbase[r] + sboff);
                        st_async(rbase[r] + po, pp, rbase[r] + sboff);
                    }
                }
            }
        }
    }
    CLUSTER_SYNC();   // no CTA exits while peers' in-flight stores may target it
}

// =======================================================================
// launch
// =======================================================================
extern "C" void kernel_launch(void* const* d_in, const int* in_sizes, int n_in,
                              void* d_out, int out_size)
{
    const float* inputs = (const float*)d_in[0];
    const float* Wa     = (const float*)d_in[1];
    const float* Ua     = (const float*)d_in[2];
    const float* Va     = (const float*)d_in[3];
    const float* Ba     = (const float*)d_in[4];
    const float* Wo     = (const float*)d_in[5];
    const float* Uo     = (const float*)d_in[6];
    const float* Co     = (const float*)d_in[7];
    const float* Bo     = (const float*)d_in[8];
    const float* emb    = (const float*)d_in[9];
    float* out = (float*)d_out;

    dim3 g(16, 8, 3);
    gemm3_kernel<<<g, 256>>>(inputs, Ua, Co, Uo, Ba);
    embwo_kernel<<<64, 256>>>(emb, Wo);

    cudaFuncSetAttribute(scan_kernel,
                         cudaFuncAttributeMaxDynamicSharedMemorySize, SMEM_BYTES);
    scan_kernel<<<BB * CPG, NTH, SMEM_BYTES>>>(Wa, Va, Bo, out);
}